// round 9
// baseline (speedup 1.0000x reference)
#include <cuda_runtime.h>
#include <cuda_bf16.h>

#define BATCH    65536
#define N_WIRES  4
#define N_LAYERS 3
#define BN_EPS   1e-5f
#define GRID     256                 // persistent blocks; 256 samples each
#define SPB      (BATCH / GRID)      // samples per block = 256
#define ITERS    (SPB / 16)          // sim iterations per block = 16

// Scratch (no cudaMalloc allowed)
__device__ float g_part[GRID * 8];         // per-block BN partials
__device__ float g_pre[BATCH * 4];         // pre-BN linear outputs
__device__ float g_stats[8];               // BN affine: A[4], B[4]
__device__ unsigned int g_ticket1;         // zero-init; reset each launch
__device__ unsigned int g_ticket2;
__device__ unsigned int g_flag;

// ---------------------------------------------------------------------------
// Single persistent kernel: phase 1 = encode + 4-qubit sim (16 lanes = 16
// amplitudes, 2 samples/warp) + Linear(4,4) + BN partials; device-wide
// barrier (ticket + flag); phase 2 = BN normalize own samples.
// ---------------------------------------------------------------------------
__global__ void __launch_bounds__(256) fused_kernel(const float* __restrict__ x,
                                                    const float* __restrict__ params,
                                                    const float* __restrict__ Wg,
                                                    const float* __restrict__ bg,
                                                    const float* __restrict__ bnw,
                                                    const float* __restrict__ bnb,
                                                    float* __restrict__ out) {
    __shared__ float sM[96];     // [l][w][row][col][ri]
    __shared__ float sAcc[8];
    __shared__ float sRed[8];
    __shared__ int   sLast;
    int tid = threadIdx.x;
    if (tid < 8) { sAcc[tid] = 0.0f; sRed[tid] = 0.0f; }
    if (tid < 12) {   // tid = l*4 + w : build fused M = RX(t1) @ RZ(t0)
        float t0 = params[tid * 3 + 0];
        float t1 = params[tid * 3 + 1];
        float c0, s0, c1, s1;
        sincosf(0.5f * t0, &s0, &c0);
        sincosf(0.5f * t1, &s1, &c1);
        float2* Mo = (float2*)sM;
        Mo[tid * 4 + 0] = make_float2( c1 * c0, -c1 * s0);
        Mo[tid * 4 + 1] = make_float2( s1 * s0, -s1 * c0);
        Mo[tid * 4 + 2] = make_float2(-s1 * s0, -s1 * c0);
        Mo[tid * 4 + 3] = make_float2( c1 * c0,  c1 * s0);
    }
    __syncthreads();

    int lane = tid & 31;
    int warp = tid >> 5;
    int g  = lane >> 3;
    int j8 = lane & 7;
    int k  = lane & 15;                // amplitude index owned by this lane
    const float2* M2 = (const float2*)sM;
    const float4* x4 = (const float4*)x;

    float oAcc = 0.0f, qAcc = 0.0f;    // per-lane BN accumulators (lanes 0-3)

    // ================= phase 1: sim over this block's 256 samples =========
    for (int it = 0; it < ITERS; it++) {
        int sA = blockIdx.x * SPB + it * 16 + warp * 2;   // samples sA, sA+1

        // ---- encoding: mean of 4 chunks of 196 floats (49 float4 each) ----
        const float4* pA = x4 + (size_t)sA * 196 + g * 49 + j8;
        float sum_a = 0.0f, sum_b = 0.0f;
#pragma unroll
        for (int q = 0; q < 6; q++) {
            float4 v = pA[q * 8];
            sum_a += (v.x + v.y) + (v.z + v.w);
            float4 u = pA[196 + q * 8];
            sum_b += (u.x + u.y) + (u.z + u.w);
        }
        if (j8 == 0) {
            float4 v = pA[48];
            sum_a += (v.x + v.y) + (v.z + v.w);
            float4 u = pA[196 + 48];
            sum_b += (u.x + u.y) + (u.z + u.w);
        }
#pragma unroll
        for (int m = 4; m >= 1; m >>= 1) {
            sum_a += __shfl_xor_sync(0xffffffffu, sum_a, m);
            sum_b += __shfl_xor_sync(0xffffffffu, sum_b, m);
        }

        float cs[4], ss[4];
#pragma unroll
        for (int w = 0; w < 4; w++) {
            float ta = __shfl_sync(0xffffffffu, sum_a, w * 8);
            float tb = __shfl_sync(0xffffffffu, sum_b, w * 8);
            float ang = ((lane < 16) ? ta : tb) * (0.5f / 196.0f);
            float c, s;
            __sincosf(ang, &s, &c);
            if ((k >> (3 - w)) & 1) s = -s;
            cs[w] = c; ss[w] = s;
        }

        // ---- statevector sim: amp(k) per lane ----
        float ar = (k == 0) ? 1.0f : 0.0f;
        float ai = 0.0f;
#pragma unroll
        for (int l = 0; l < N_LAYERS; l++) {
#pragma unroll
            for (int w = 0; w < 4; w++) {
                int b = (k >> (3 - w)) & 1;
                float2 ma = M2[(l * 4 + w) * 4 + b * 3];      // M[b][b]
                float2 mp = M2[(l * 4 + w) * 4 + b + 1];      // M[b][1-b]
                float c = cs[w], s = ss[w];
                float uar = ma.x * c + mp.x * s;
                float uai = ma.y * c + mp.y * s;
                float upr = mp.x * c - ma.x * s;
                float upi = mp.y * c - ma.y * s;
                float pr = __shfl_xor_sync(0xffffffffu, ar, 8 >> w);
                float pi = __shfl_xor_sync(0xffffffffu, ai, 8 >> w);
                float nr = uar * ar - uai * ai + upr * pr - upi * pi;
                float ni = uar * ai + uai * ar + upr * pi + upi * pr;
                ar = nr; ai = ni;
                if (w < 3) {   // CNOT(w, w+1)
                    int cm = 8 >> w, tm = 4 >> w;
                    int src = (k & cm) ? (lane ^ tm) : lane;
                    ar = __shfl_sync(0xffffffffu, ar, src);
                    ai = __shfl_sync(0xffffffffu, ai, src);
                }
            }
        }

        // ---- PauliZ expvals ----
        float p = ar * ar + ai * ai;
        float z[4];
#pragma unroll
        for (int w = 0; w < 4; w++) {
            float v = ((k >> (3 - w)) & 1) ? -p : p;
            v += __shfl_xor_sync(0xffffffffu, v, 1);
            v += __shfl_xor_sync(0xffffffffu, v, 2);
            v += __shfl_xor_sync(0xffffffffu, v, 4);
            v += __shfl_xor_sync(0xffffffffu, v, 8);
            z[w] = v;
        }

        // ---- Linear(4,4) ----
        float o = 0.0f, q = 0.0f;
        if (k < 4) {
            float4 Wr = ((const float4*)Wg)[k];
            o = bg[k] + Wr.x * z[0] + Wr.y * z[1] + Wr.z * z[2] + Wr.w * z[3];
            int s = (lane < 16) ? sA : (sA + 1);
            g_pre[s * 4 + k] = o;
            q = o * o;
        }
        float o2 = __shfl_xor_sync(0xffffffffu, o, 16);
        float q2 = __shfl_xor_sync(0xffffffffu, q, 16);
        if (lane < 4) { oAcc += o + o2; qAcc += q + q2; }
    }

    // ---- block-level BN partials ----
    if (lane < 4) {
        atomicAdd(&sAcc[lane],     oAcc);
        atomicAdd(&sAcc[lane + 4], qAcc);
    }
    __syncthreads();
    if (tid < 8) g_part[blockIdx.x * 8 + tid] = sAcc[tid];

    // ================= device-wide barrier (ticket + flag) =================
    if (tid == 0) {
        __threadfence();                                // publish g_part / g_pre
        unsigned int t = atomicAdd(&g_ticket1, 1u);
        sLast = (t == GRID - 1) ? 1 : 0;
    }
    __syncthreads();
    if (sLast) {
        __threadfence();                                // acquire all partials
        // 256 rows of 8 floats: thread t reduces row t
        float a[8] = {0, 0, 0, 0, 0, 0, 0, 0};
        const float4* p4 = (const float4*)g_part;
        {
            float4 lo = p4[tid * 2 + 0];
            float4 hi = p4[tid * 2 + 1];
            a[0] = lo.x; a[1] = lo.y; a[2] = lo.z; a[3] = lo.w;
            a[4] = hi.x; a[5] = hi.y; a[6] = hi.z; a[7] = hi.w;
        }
#pragma unroll
        for (int j = 0; j < 8; j++) {
#pragma unroll
            for (int m = 16; m >= 1; m >>= 1)
                a[j] += __shfl_xor_sync(0xffffffffu, a[j], m);
        }
        if ((tid & 31) == 0) {
#pragma unroll
            for (int j = 0; j < 8; j++) atomicAdd(&sRed[j], a[j]);
        }
        __syncthreads();
        if (tid < 4) {
            const float inv = 1.0f / (float)BATCH;
            float mu  = sRed[tid] * inv;
            float var = sRed[tid + 4] * inv - mu * mu;
            float rs  = rsqrtf(var + BN_EPS) * bnw[tid];
            g_stats[tid]     = rs;                      // A
            g_stats[tid + 4] = bnb[tid] - mu * rs;      // B
        }
        __syncthreads();
        if (tid == 0) {
            __threadfence();                            // publish g_stats
            atomicExch(&g_flag, 1u);                    // release
        }
    }
    if (tid == 0) {
        volatile unsigned int* f = &g_flag;
        while (*f == 0u) { __nanosleep(64); }
    }
    __syncthreads();
    __threadfence();                                    // acquire g_stats

    // ================= phase 2: normalize own 256 samples ==================
    float a0 = g_stats[0], a1 = g_stats[1], a2 = g_stats[2], a3 = g_stats[3];
    float b0 = g_stats[4], b1 = g_stats[5], b2 = g_stats[6], b3 = g_stats[7];
    int i = blockIdx.x * SPB + tid;                     // one sample (float4)
    float4 v = ((const float4*)g_pre)[i];
    float4 r;
    r.x = v.x * a0 + b0;
    r.y = v.y * a1 + b1;
    r.z = v.z * a2 + b2;
    r.w = v.w * a3 + b3;
    ((float4*)out)[i] = r;

    // ---- reset counters for next graph replay (last block to finish) ----
    __syncthreads();
    if (tid == 0) {
        unsigned int t2 = atomicAdd(&g_ticket2, 1u);
        if (t2 == GRID - 1) {
            g_ticket1 = 0u;
            g_ticket2 = 0u;
            g_flag    = 0u;
            __threadfence();
        }
    }
}

// ---------------------------------------------------------------------------
extern "C" void kernel_launch(void* const* d_in, const int* in_sizes, int n_in,
                              void* d_out, int out_size) {
    const float* x      = (const float*)d_in[0];
    const float* params = (const float*)d_in[1];
    const float* W      = (const float*)d_in[2];
    const float* b      = (const float*)d_in[3];
    const float* bnw    = (const float*)d_in[4];
    const float* bnb    = (const float*)d_in[5];
    float* out = (float*)d_out;

    fused_kernel<<<GRID, 256>>>(x, params, W, b, bnw, bnb, out);
}

// round 14
// speedup vs baseline: 1.2880x; 1.2880x over previous
#include <cuda_runtime.h>
#include <cuda_bf16.h>

#define BATCH    65536
#define N_WIRES  4
#define N_LAYERS 3
#define BN_EPS   1e-5f
#define GRID     512                 // persistent blocks; co-resident (<=4/SM @48regs, cap 5)
#define SPB      (BATCH / GRID)      // samples per block = 128
#define ITERS    (SPB / 16)          // sim iterations per block = 8

// Scratch (no cudaMalloc allowed)
__device__ float g_part[GRID * 8];         // per-block BN partials
__device__ float g_pre[BATCH * 4];         // pre-BN linear outputs
__device__ float g_stats[8];               // BN affine: A[4], B[4]
__device__ unsigned int g_ticket1;         // zero-init; reset each launch
__device__ unsigned int g_ticket2;
__device__ unsigned int g_flag;

// ---------------------------------------------------------------------------
// Single persistent kernel: phase 1 = encode + 4-qubit sim (16 lanes = 16
// amplitudes, 2 samples/warp) + Linear(4,4) + BN partials; device-wide
// barrier (ticket + flag); phase 2 = BN normalize own samples.
// ---------------------------------------------------------------------------
__global__ void __launch_bounds__(256) fused_kernel(const float* __restrict__ x,
                                                    const float* __restrict__ params,
                                                    const float* __restrict__ Wg,
                                                    const float* __restrict__ bg,
                                                    const float* __restrict__ bnw,
                                                    const float* __restrict__ bnb,
                                                    float* __restrict__ out) {
    __shared__ float sM[96];     // [l][w][row][col][ri]
    __shared__ float sAcc[8];
    __shared__ float sRed[8];
    __shared__ int   sLast;
    int tid = threadIdx.x;
    if (tid < 8) { sAcc[tid] = 0.0f; sRed[tid] = 0.0f; }
    if (tid < 12) {   // tid = l*4 + w : build fused M = RX(t1) @ RZ(t0)
        float t0 = params[tid * 3 + 0];
        float t1 = params[tid * 3 + 1];
        float c0, s0, c1, s1;
        sincosf(0.5f * t0, &s0, &c0);
        sincosf(0.5f * t1, &s1, &c1);
        float2* Mo = (float2*)sM;
        Mo[tid * 4 + 0] = make_float2( c1 * c0, -c1 * s0);
        Mo[tid * 4 + 1] = make_float2( s1 * s0, -s1 * c0);
        Mo[tid * 4 + 2] = make_float2(-s1 * s0, -s1 * c0);
        Mo[tid * 4 + 3] = make_float2( c1 * c0,  c1 * s0);
    }
    __syncthreads();

    int lane = tid & 31;
    int warp = tid >> 5;
    int g  = lane >> 3;
    int j8 = lane & 7;
    int k  = lane & 15;                // amplitude index owned by this lane
    const float2* M2 = (const float2*)sM;
    const float4* x4 = (const float4*)x;

    float oAcc = 0.0f, qAcc = 0.0f;    // per-lane BN accumulators (lanes 0-3)

    // ================= phase 1: sim over this block's 128 samples =========
    for (int it = 0; it < ITERS; it++) {
        int sA = blockIdx.x * SPB + it * 16 + warp * 2;   // samples sA, sA+1

        // ---- encoding: mean of 4 chunks of 196 floats (49 float4 each) ----
        const float4* pA = x4 + (size_t)sA * 196 + g * 49 + j8;
        float sum_a = 0.0f, sum_b = 0.0f;
#pragma unroll
        for (int q = 0; q < 6; q++) {
            float4 v = pA[q * 8];
            sum_a += (v.x + v.y) + (v.z + v.w);
            float4 u = pA[196 + q * 8];
            sum_b += (u.x + u.y) + (u.z + u.w);
        }
        if (j8 == 0) {
            float4 v = pA[48];
            sum_a += (v.x + v.y) + (v.z + v.w);
            float4 u = pA[196 + 48];
            sum_b += (u.x + u.y) + (u.z + u.w);
        }
#pragma unroll
        for (int m = 4; m >= 1; m >>= 1) {
            sum_a += __shfl_xor_sync(0xffffffffu, sum_a, m);
            sum_b += __shfl_xor_sync(0xffffffffu, sum_b, m);
        }

        float cs[4], ss[4];
#pragma unroll
        for (int w = 0; w < 4; w++) {
            float ta = __shfl_sync(0xffffffffu, sum_a, w * 8);
            float tb = __shfl_sync(0xffffffffu, sum_b, w * 8);
            float ang = ((lane < 16) ? ta : tb) * (0.5f / 196.0f);
            float c, s;
            __sincosf(ang, &s, &c);
            if ((k >> (3 - w)) & 1) s = -s;
            cs[w] = c; ss[w] = s;
        }

        // ---- statevector sim: amp(k) per lane ----
        float ar = (k == 0) ? 1.0f : 0.0f;
        float ai = 0.0f;
#pragma unroll
        for (int l = 0; l < N_LAYERS; l++) {
#pragma unroll
            for (int w = 0; w < 4; w++) {
                int b = (k >> (3 - w)) & 1;
                float2 ma = M2[(l * 4 + w) * 4 + b * 3];      // M[b][b]
                float2 mp = M2[(l * 4 + w) * 4 + b + 1];      // M[b][1-b]
                float c = cs[w], s = ss[w];
                float uar = ma.x * c + mp.x * s;
                float uai = ma.y * c + mp.y * s;
                float upr = mp.x * c - ma.x * s;
                float upi = mp.y * c - ma.y * s;
                float pr = __shfl_xor_sync(0xffffffffu, ar, 8 >> w);
                float pi = __shfl_xor_sync(0xffffffffu, ai, 8 >> w);
                float nr = uar * ar - uai * ai + upr * pr - upi * pi;
                float ni = uar * ai + uai * ar + upr * pi + upi * pr;
                ar = nr; ai = ni;
                if (w < 3) {   // CNOT(w, w+1)
                    int cm = 8 >> w, tm = 4 >> w;
                    int src = (k & cm) ? (lane ^ tm) : lane;
                    ar = __shfl_sync(0xffffffffu, ar, src);
                    ai = __shfl_sync(0xffffffffu, ai, src);
                }
            }
        }

        // ---- PauliZ expvals ----
        float p = ar * ar + ai * ai;
        float z[4];
#pragma unroll
        for (int w = 0; w < 4; w++) {
            float v = ((k >> (3 - w)) & 1) ? -p : p;
            v += __shfl_xor_sync(0xffffffffu, v, 1);
            v += __shfl_xor_sync(0xffffffffu, v, 2);
            v += __shfl_xor_sync(0xffffffffu, v, 4);
            v += __shfl_xor_sync(0xffffffffu, v, 8);
            z[w] = v;
        }

        // ---- Linear(4,4) ----
        float o = 0.0f, q = 0.0f;
        if (k < 4) {
            float4 Wr = ((const float4*)Wg)[k];
            o = bg[k] + Wr.x * z[0] + Wr.y * z[1] + Wr.z * z[2] + Wr.w * z[3];
            int s = (lane < 16) ? sA : (sA + 1);
            g_pre[s * 4 + k] = o;
            q = o * o;
        }
        float o2 = __shfl_xor_sync(0xffffffffu, o, 16);
        float q2 = __shfl_xor_sync(0xffffffffu, q, 16);
        if (lane < 4) { oAcc += o + o2; qAcc += q + q2; }
    }

    // ---- block-level BN partials ----
    if (lane < 4) {
        atomicAdd(&sAcc[lane],     oAcc);
        atomicAdd(&sAcc[lane + 4], qAcc);
    }
    __syncthreads();
    if (tid < 8) g_part[blockIdx.x * 8 + tid] = sAcc[tid];

    // ================= device-wide barrier (ticket + flag) =================
    if (tid == 0) {
        __threadfence();                                // publish g_part / g_pre
        unsigned int t = atomicAdd(&g_ticket1, 1u);
        sLast = (t == GRID - 1) ? 1 : 0;
    }
    __syncthreads();
    if (sLast) {
        __threadfence();                                // acquire all partials
        // 512 rows of 8 floats: thread t reduces rows 2t, 2t+1
        float a[8];
        const float4* p4 = (const float4*)g_part;
        {
            float4 lo0 = p4[tid * 4 + 0];
            float4 hi0 = p4[tid * 4 + 1];
            float4 lo1 = p4[tid * 4 + 2];
            float4 hi1 = p4[tid * 4 + 3];
            a[0] = lo0.x + lo1.x; a[1] = lo0.y + lo1.y;
            a[2] = lo0.z + lo1.z; a[3] = lo0.w + lo1.w;
            a[4] = hi0.x + hi1.x; a[5] = hi0.y + hi1.y;
            a[6] = hi0.z + hi1.z; a[7] = hi0.w + hi1.w;
        }
#pragma unroll
        for (int j = 0; j < 8; j++) {
#pragma unroll
            for (int m = 16; m >= 1; m >>= 1)
                a[j] += __shfl_xor_sync(0xffffffffu, a[j], m);
        }
        if ((tid & 31) == 0) {
#pragma unroll
            for (int j = 0; j < 8; j++) atomicAdd(&sRed[j], a[j]);
        }
        __syncthreads();
        if (tid < 4) {
            const float inv = 1.0f / (float)BATCH;
            float mu  = sRed[tid] * inv;
            float var = sRed[tid + 4] * inv - mu * mu;
            float rs  = rsqrtf(var + BN_EPS) * bnw[tid];
            g_stats[tid]     = rs;                      // A
            g_stats[tid + 4] = bnb[tid] - mu * rs;      // B
        }
        __syncthreads();
        if (tid == 0) {
            __threadfence();                            // publish g_stats
            atomicExch(&g_flag, 1u);                    // release
        }
    }
    if (tid == 0) {
        volatile unsigned int* f = &g_flag;
        while (*f == 0u) { __nanosleep(64); }
    }
    __syncthreads();
    __threadfence();                                    // acquire g_stats

    // ================= phase 2: normalize own 128 samples ==================
    float a0 = g_stats[0], a1 = g_stats[1], a2 = g_stats[2], a3 = g_stats[3];
    float b0 = g_stats[4], b1 = g_stats[5], b2 = g_stats[6], b3 = g_stats[7];
    if (tid < SPB) {
        int i = blockIdx.x * SPB + tid;                 // one sample (float4)
        float4 v = ((const float4*)g_pre)[i];
        float4 r;
        r.x = v.x * a0 + b0;
        r.y = v.y * a1 + b1;
        r.z = v.z * a2 + b2;
        r.w = v.w * a3 + b3;
        ((float4*)out)[i] = r;
    }

    // ---- reset counters for next graph replay (last block to finish) ----
    __syncthreads();
    if (tid == 0) {
        unsigned int t2 = atomicAdd(&g_ticket2, 1u);
        if (t2 == GRID - 1) {
            g_ticket1 = 0u;
            g_ticket2 = 0u;
            g_flag    = 0u;
            __threadfence();
        }
    }
}

// ---------------------------------------------------------------------------
extern "C" void kernel_launch(void* const* d_in, const int* in_sizes, int n_in,
                              void* d_out, int out_size) {
    const float* x      = (const float*)d_in[0];
    const float* params = (const float*)d_in[1];
    const float* W      = (const float*)d_in[2];
    const float* b      = (const float*)d_in[3];
    const float* bnw    = (const float*)d_in[4];
    const float* bnb    = (const float*)d_in[5];
    float* out = (float*)d_out;

    fused_kernel<<<GRID, 256>>>(x, params, W, b, bnw, bnb, out);
}